// round 1
// baseline (speedup 1.0000x reference)
#include <cuda_runtime.h>

#define T_LEN 32768
#define D_IN  512
#define HID   20
#define G4    80   // 4*HID

// Scratch (static device arrays; no allocation)
__device__ float g_xg[T_LEN * G4];   // precomputed input gate contributions
__device__ float g_h [T_LEN * HID]; // hidden states per step

// ---------------------------------------------------------------------------
// Kernel A: xg[t][g] = sum_k x[t][k] * W_ih[g][k] + (b_ih[g] + b_hh[g])
// Block: 256 threads, 64 rows of t per block. Tiled over k in chunks of 64.
// Thread owns 4 rows x 5 gates (20 accumulators).
// ---------------------------------------------------------------------------
__global__ void gemm_xg_kernel(const float* __restrict__ x,
                               const float* __restrict__ W_ih,
                               const float* __restrict__ b_ih,
                               const float* __restrict__ b_hh) {
    __shared__ float xs[64][64];
    __shared__ float ws[80][65];   // +1 pad: avoids bank conflicts on gate-strided reads

    const int tid = threadIdx.x;
    const int t0  = blockIdx.x * 64;
    const int rg  = tid >> 4;   // 0..15 row group (4 rows each)
    const int gg  = tid & 15;   // 0..15 gate group (5 gates each)

    float acc[4][5];
#pragma unroll
    for (int r = 0; r < 4; ++r)
#pragma unroll
        for (int i = 0; i < 5; ++i) acc[r][i] = 0.f;

    const float4* x4 = (const float4*)x;

    for (int kc = 0; kc < D_IN; kc += 64) {
        // load x tile: 64 rows x 64 cols = 1024 float4
#pragma unroll
        for (int it = 0; it < 4; ++it) {
            int idx = tid + it * 256;
            int row = idx >> 4;
            int c4  = idx & 15;
            float4 v = x4[(size_t)(t0 + row) * (D_IN / 4) + (kc >> 2) + c4];
            *(float4*)&xs[row][c4 * 4] = v;
        }
        // load W tile: 80 x 64 floats
#pragma unroll
        for (int it = 0; it < 20; ++it) {
            int idx = tid + it * 256;
            int gq  = idx >> 6;
            int kk  = idx & 63;
            ws[gq][kk] = W_ih[gq * D_IN + kc + kk];
        }
        __syncthreads();

#pragma unroll 4
        for (int k = 0; k < 64; ++k) {
            float xv[4], wv[5];
#pragma unroll
            for (int r = 0; r < 4; ++r) xv[r] = xs[rg * 4 + r][k];
#pragma unroll
            for (int i = 0; i < 5; ++i) wv[i] = ws[gg * 5 + i][k];
#pragma unroll
            for (int r = 0; r < 4; ++r)
#pragma unroll
                for (int i = 0; i < 5; ++i)
                    acc[r][i] = fmaf(xv[r], wv[i], acc[r][i]);
        }
        __syncthreads();
    }

#pragma unroll
    for (int r = 0; r < 4; ++r) {
        int row = t0 + rg * 4 + r;
#pragma unroll
        for (int i = 0; i < 5; ++i) {
            int gate = gg * 5 + i;
            g_xg[(size_t)row * G4 + gate] = acc[r][i] + b_ih[gate] + b_hh[gate];
        }
    }
}

// ---------------------------------------------------------------------------
// Kernel B: the sequential LSTM scan. Single block, 96 threads (3 warps).
//   threads 0..79 : compute gate pre-activations + activation
//   threads 0..19 : c/h update, write h to g_h
// Unified activation: A/(1+exp(-A*x)) + C  (A=1,C=0 sigmoid; A=2,C=-1 tanh)
// ---------------------------------------------------------------------------
__global__ void __launch_bounds__(96, 1)
lstm_scan_kernel(const float* __restrict__ h_state,
                 const float* __restrict__ c_state,
                 const float* __restrict__ W_hh,
                 float* __restrict__ out) {
    __shared__ float h_sm[HID];
    __shared__ float gates[G4];

    const int j = threadIdx.x;

    // per-lane weights (W_hh row) in registers
    float w[HID];
    if (j < G4) {
#pragma unroll
        for (int k = 0; k < HID; ++k) w[k] = W_hh[j * HID + k];
    }

    // per-lane activation constants (tanh only for gates 40..59)
    const bool is_g = (j >= 40 && j < 60);
    const float Aa = is_g ? 2.f : 1.f;
    const float Cc = is_g ? -1.f : 0.f;

    float c = 0.f, hreg = 0.f;
    if (j < HID) {
        c = c_state[j];
        h_sm[j] = h_state[j];
    }

    float xv = 0.f;
    if (j < G4) xv = g_xg[j];
    __syncthreads();

    for (int t = 0; t < T_LEN; ++t) {
        float xv_next = 0.f;
        if (j < G4) {
            // prefetch next step's xg early (covers L2 latency)
            int tn = (t + 1 < T_LEN) ? t + 1 : T_LEN - 1;
            xv_next = g_xg[(size_t)tn * G4 + j];

            // gate pre-activation: xv + W_hh[j,:] . h
            float a0 = xv, a1 = 0.f;
#pragma unroll
            for (int k = 0; k < HID; k += 2) {
                a0 = fmaf(w[k],     h_sm[k],     a0);
                a1 = fmaf(w[k + 1], h_sm[k + 1], a1);
            }
            float gsum = a0 + a1;
            float act = Aa * __fdividef(1.f, 1.f + __expf(-Aa * gsum)) + Cc;
            gates[j] = act;
        }
        xv = xv_next;
        __syncthreads();

        if (j < HID) {
            float i_ = gates[j];
            float f_ = gates[j + 20];
            float g_ = gates[j + 40];
            float o_ = gates[j + 60];
            c = fmaf(f_, c, i_ * g_);
            float th = 2.f * __fdividef(1.f, 1.f + __expf(-2.f * c)) - 1.f;
            hreg = o_ * th;
            h_sm[j] = hreg;
            g_h[(size_t)t * HID + j] = hreg;   // fire-and-forget
        }
        __syncthreads();
    }

    // final states: out layout = [y(T) | h_T(20) | c_T(20)]
    if (j < HID) {
        out[T_LEN + j]       = hreg;
        out[T_LEN + HID + j] = c;
    }
}

// ---------------------------------------------------------------------------
// Kernel C: y[t] = h[t,:] . W_out + b_out   (fully parallel)
// ---------------------------------------------------------------------------
__global__ void out_proj_kernel(const float* __restrict__ W_out,
                                const float* __restrict__ b_out,
                                float* __restrict__ out) {
    __shared__ float w[HID];
    __shared__ float b0;
    if (threadIdx.x < HID) w[threadIdx.x] = W_out[threadIdx.x];
    if (threadIdx.x == 0)  b0 = b_out[0];
    __syncthreads();

    int t = blockIdx.x * blockDim.x + threadIdx.x;
    if (t < T_LEN) {
        const float4* hv = (const float4*)(g_h + (size_t)t * HID);
        float acc = 0.f;
#pragma unroll
        for (int q = 0; q < 5; ++q) {
            float4 v = hv[q];
            acc = fmaf(v.x, w[q * 4 + 0], acc);
            acc = fmaf(v.y, w[q * 4 + 1], acc);
            acc = fmaf(v.z, w[q * 4 + 2], acc);
            acc = fmaf(v.w, w[q * 4 + 3], acc);
        }
        out[t] = acc + b0;
    }
}

// ---------------------------------------------------------------------------
extern "C" void kernel_launch(void* const* d_in, const int* in_sizes, int n_in,
                              void* d_out, int out_size) {
    const float* x       = (const float*)d_in[0];
    const float* h_state = (const float*)d_in[1];
    const float* c_state = (const float*)d_in[2];
    const float* W_ih    = (const float*)d_in[3];
    const float* W_hh    = (const float*)d_in[4];
    const float* b_ih    = (const float*)d_in[5];
    const float* b_hh    = (const float*)d_in[6];
    const float* W_out   = (const float*)d_in[7];
    const float* b_out   = (const float*)d_in[8];
    float* out = (float*)d_out;

    gemm_xg_kernel<<<T_LEN / 64, 256>>>(x, W_ih, b_ih, b_hh);
    lstm_scan_kernel<<<1, 96>>>(h_state, c_state, W_hh, out);
    out_proj_kernel<<<(T_LEN + 255) / 256, 256>>>(W_out, b_out, out);
}

// round 2
// speedup vs baseline: 1.5247x; 1.5247x over previous
#include <cuda_runtime.h>

#define T_LEN 32768
#define D_IN  512
#define HID   20
#define G4    80   // 4*HID

// Scratch (static device arrays; no allocation)
// Layout: g_xg[t*80 + unit*4 + {i,f,g,o}]  (gate-interleaved per unit)
__device__ float g_xg[T_LEN * G4];
__device__ float g_h [T_LEN * HID];

// ---------------- f32x2 packed helpers (sm_100+) ----------------
typedef unsigned long long ull;

__device__ __forceinline__ ull pack2(float lo, float hi) {
    ull r;
    asm("mov.b64 %0, {%1, %2};" : "=l"(r) : "f"(lo), "f"(hi));
    return r;
}
__device__ __forceinline__ void unpack2(ull v, float& lo, float& hi) {
    asm("mov.b64 {%0, %1}, %2;" : "=f"(lo), "=f"(hi) : "l"(v));
}
__device__ __forceinline__ void ffma2(ull& acc, ull a, ull b) {
    asm("fma.rn.f32x2 %0, %1, %2, %0;" : "+l"(acc) : "l"(a), "l"(b));
}
__device__ __forceinline__ ull fadd2(ull a, ull b) {
    ull r;
    asm("add.rn.f32x2 %0, %1, %2;" : "=l"(r) : "l"(a), "l"(b));
    return r;
}

__device__ __forceinline__ float fast_sigmoid(float x) {
    return __fdividef(1.f, 1.f + __expf(-x));
}

// ---------------------------------------------------------------------------
// Kernel A: xg[t][unit][q] = sum_k x[t][k]*W_ih[q*20+unit][k] + bias
// ---------------------------------------------------------------------------
__global__ void gemm_xg_kernel(const float* __restrict__ x,
                               const float* __restrict__ W_ih,
                               const float* __restrict__ b_ih,
                               const float* __restrict__ b_hh) {
    __shared__ float xs[64][64];
    __shared__ float ws[80][65];

    const int tid = threadIdx.x;
    const int t0  = blockIdx.x * 64;
    const int rg  = tid >> 4;   // 0..15 row group (4 rows each)
    const int gg  = tid & 15;   // 0..15 gate group (5 gates each)

    float acc[4][5];
#pragma unroll
    for (int r = 0; r < 4; ++r)
#pragma unroll
        for (int i = 0; i < 5; ++i) acc[r][i] = 0.f;

    const float4* x4 = (const float4*)x;

    for (int kc = 0; kc < D_IN; kc += 64) {
#pragma unroll
        for (int it = 0; it < 4; ++it) {
            int idx = tid + it * 256;
            int row = idx >> 4;
            int c4  = idx & 15;
            float4 v = x4[(size_t)(t0 + row) * (D_IN / 4) + (kc >> 2) + c4];
            *(float4*)&xs[row][c4 * 4] = v;
        }
#pragma unroll
        for (int it = 0; it < 20; ++it) {
            int idx = tid + it * 256;
            int gq  = idx >> 6;
            int kk  = idx & 63;
            ws[gq][kk] = W_ih[gq * D_IN + kc + kk];
        }
        __syncthreads();

#pragma unroll 4
        for (int k = 0; k < 64; ++k) {
            float xv[4], wv[5];
#pragma unroll
            for (int r = 0; r < 4; ++r) xv[r] = xs[rg * 4 + r][k];
#pragma unroll
            for (int i = 0; i < 5; ++i) wv[i] = ws[gg * 5 + i][k];
#pragma unroll
            for (int r = 0; r < 4; ++r)
#pragma unroll
                for (int i = 0; i < 5; ++i)
                    acc[r][i] = fmaf(xv[r], wv[i], acc[r][i]);
        }
        __syncthreads();
    }

#pragma unroll
    for (int r = 0; r < 4; ++r) {
        int row = t0 + rg * 4 + r;
#pragma unroll
        for (int i = 0; i < 5; ++i) {
            int gate = gg * 5 + i;        // original index: q*20 + unit
            int q    = gate / HID;
            int unit = gate % HID;
            g_xg[(size_t)row * G4 + unit * 4 + q] =
                acc[r][i] + b_ih[gate] + b_hh[gate];
        }
    }
}

// ---------------------------------------------------------------------------
// Kernel B: single-WARP LSTM scan. Lane j owns hidden unit j (j<20).
// Zero barriers: h exchanged via shfl. Packed f32x2 FMAs.
// ---------------------------------------------------------------------------
__global__ void __launch_bounds__(32, 1)
lstm_scan_kernel(const float* __restrict__ h_state,
                 const float* __restrict__ c_state,
                 const float* __restrict__ W_hh,
                 float* __restrict__ out) {
    const int j  = threadIdx.x;
    const int jj = (j < HID) ? j : HID - 1;   // lanes 20..31 mirror lane 19

    // Packed weights: w_if[k] = (W_hh[j][k], W_hh[j+20][k])
    //                 w_go[k] = (W_hh[j+40][k], W_hh[j+60][k])
    ull w_if[HID], w_go[HID];
#pragma unroll
    for (int k = 0; k < HID; ++k) {
        w_if[k] = pack2(W_hh[jj * HID + k],        W_hh[(jj + 20) * HID + k]);
        w_go[k] = pack2(W_hh[(jj + 40) * HID + k], W_hh[(jj + 60) * HID + k]);
    }

    float c = c_state[jj];
    float h = h_state[jj];

    const float4* xg4 = (const float4*)g_xg;

    // prefetch pipeline (depth 2, covers L2 latency > step time)
    float4 buf0 = __ldg(&xg4[0 * HID + jj]);
    float4 buf1 = __ldg(&xg4[1 * HID + jj]);

    for (int t = 0; t < T_LEN; ++t) {
        const float4 xv = buf0;
        buf0 = buf1;
        int tp = (t + 2 < T_LEN) ? t + 2 : T_LEN - 1;
        buf1 = __ldg(&xg4[(size_t)tp * HID + jj]);

        // 4 interleaved accumulator chains (even/odd split, 10 deep each)
        ull a_if0 = pack2(xv.x, xv.y), a_if1 = pack2(0.f, 0.f);
        ull a_go0 = pack2(xv.z, xv.w), a_go1 = pack2(0.f, 0.f);
#pragma unroll
        for (int k = 0; k < HID; k += 2) {
            float h0 = __shfl_sync(0xffffffffu, h, k);
            float h1 = __shfl_sync(0xffffffffu, h, k + 1);
            ull hh0 = pack2(h0, h0);
            ull hh1 = pack2(h1, h1);
            ffma2(a_if0, w_if[k],     hh0);
            ffma2(a_go0, w_go[k],     hh0);
            ffma2(a_if1, w_if[k + 1], hh1);
            ffma2(a_go1, w_go[k + 1], hh1);
        }
        ull a_if = fadd2(a_if0, a_if1);
        ull a_go = fadd2(a_go0, a_go1);

        float pi, pf, pg, po;
        unpack2(a_if, pi, pf);
        unpack2(a_go, pg, po);

        float i_s = fast_sigmoid(pi);
        float f_s = fast_sigmoid(pf);
        float o_s = fast_sigmoid(po);
        float g_t = fmaf(2.f, fast_sigmoid(2.f * pg), -1.f);   // tanh

        c = fmaf(f_s, c, i_s * g_t);
        float th = fmaf(2.f, fast_sigmoid(2.f * c), -1.f);     // tanh(c)
        h = o_s * th;

        if (j < HID)
            g_h[(size_t)t * HID + j] = h;   // fire-and-forget
    }

    if (j < HID) {
        out[T_LEN + j]       = h;
        out[T_LEN + HID + j] = c;
    }
}

// ---------------------------------------------------------------------------
// Kernel C: y[t] = h[t,:] . W_out + b_out
// ---------------------------------------------------------------------------
__global__ void out_proj_kernel(const float* __restrict__ W_out,
                                const float* __restrict__ b_out,
                                float* __restrict__ out) {
    __shared__ float w[HID];
    __shared__ float b0;
    if (threadIdx.x < HID) w[threadIdx.x] = W_out[threadIdx.x];
    if (threadIdx.x == 0)  b0 = b_out[0];
    __syncthreads();

    int t = blockIdx.x * blockDim.x + threadIdx.x;
    if (t < T_LEN) {
        const float4* hv = (const float4*)(g_h + (size_t)t * HID);
        float acc = 0.f;
#pragma unroll
        for (int q = 0; q < 5; ++q) {
            float4 v = hv[q];
            acc = fmaf(v.x, w[q * 4 + 0], acc);
            acc = fmaf(v.y, w[q * 4 + 1], acc);
            acc = fmaf(v.z, w[q * 4 + 2], acc);
            acc = fmaf(v.w, w[q * 4 + 3], acc);
        }
        out[t] = acc + b0;
    }
}

// ---------------------------------------------------------------------------
extern "C" void kernel_launch(void* const* d_in, const int* in_sizes, int n_in,
                              void* d_out, int out_size) {
    const float* x       = (const float*)d_in[0];
    const float* h_state = (const float*)d_in[1];
    const float* c_state = (const float*)d_in[2];
    const float* W_ih    = (const float*)d_in[3];
    const float* W_hh    = (const float*)d_in[4];
    const float* b_ih    = (const float*)d_in[5];
    const float* b_hh    = (const float*)d_in[6];
    const float* W_out   = (const float*)d_in[7];
    const float* b_out   = (const float*)d_in[8];
    float* out = (float*)d_out;

    gemm_xg_kernel<<<T_LEN / 64, 256>>>(x, W_ih, b_ih, b_hh);
    lstm_scan_kernel<<<1, 32>>>(h_state, c_state, W_hh, out);
    out_proj_kernel<<<(T_LEN + 255) / 256, 256>>>(W_out, b_out, out);
}